// round 4
// baseline (speedup 1.0000x reference)
#include <cuda_runtime.h>
#include <cstdint>

// ---------------------------------------------------------------------------
// NeuralSpline R4: 128-thr double-buffered conv32 w/ gmem-resident weights.
// ---------------------------------------------------------------------------

#define EPSF 1e-5f

static __device__ float g_buf1[64 * 32 * 127 * 128 + 64];
static __device__ float g_buf2[64 * 32 * 63 * 64 + 64];
static __device__ float g_buf3[64 * 32 * 31 * 32 + 64];
static __device__ float g_buf4[64 * 32 * 15 * 16 + 64];
static __device__ float g_buf5[64 * 32 * 7 * 8 + 64];
static __device__ float g_wt1[27 * 32];
static __device__ float g_wtl[4 * 288 * 32];
static __device__ float g_bns[5 * 32];
static __device__ float g_bsh[5 * 32];
static __device__ float g_coef[64 * 27];

// ---- packed f32x2 helpers ---------------------------------------------------
__device__ __forceinline__ unsigned long long pk2(float x) {
    unsigned long long r;
    unsigned u = __float_as_uint(x);
    asm("mov.b64 %0, {%1, %1};" : "=l"(r) : "r"(u));
    return r;
}
__device__ __forceinline__ void ffma2(unsigned long long& a, unsigned long long x,
                                      unsigned long long w) {
    asm("fma.rn.f32x2 %0, %1, %2, %0;" : "+l"(a) : "l"(x), "l"(w));
}
__device__ __forceinline__ float lo32(unsigned long long v) {
    return __uint_as_float((unsigned)(v & 0xffffffffULL));
}
__device__ __forceinline__ float hi32(unsigned long long v) {
    return __uint_as_float((unsigned)(v >> 32));
}

// ---------------------------------------------------------------------------
__global__ void prep_kernel(const float* __restrict__ c1w, const float* __restrict__ cw,
                            const float* __restrict__ bng, const float* __restrict__ bnb,
                            const float* __restrict__ bnm, const float* __restrict__ bnv) {
    const int stride = gridDim.x * blockDim.x;
    const int t0 = blockIdx.x * blockDim.x + threadIdx.x;
    for (int i = t0; i < 5 * 32; i += stride) {
        float inv = bng[i] * rsqrtf(bnv[i] + EPSF);
        g_bns[i] = inv;
        g_bsh[i] = bnb[i] - bnm[i] * inv;
    }
    for (int i = t0; i < 27 * 32; i += stride) {
        int oc = i / 27, r = i % 27;
        g_wt1[r * 32 + oc] = c1w[i];
    }
    for (int i = t0; i < 4 * 32 * 288; i += stride) {
        int l = i / 9216, rem = i % 9216;
        int oc = rem / 288, r = rem % 288;
        g_wtl[l * 9216 + r * 32 + oc] = cw[i];
    }
}

// 48 FFMA2 for one (ic,kh) row unit; weights read via uniform LDG.128 (pw in
// gmem, L1-resident) or smem — pointer-agnostic.
__device__ __forceinline__ void conv_row_taps(unsigned long long (&acc)[16],
                                              const float4 ev, const float e4,
                                              const float4 od,
                                              const float* __restrict__ pw) {
    unsigned long long pe0 = pk2(ev.x), pe1 = pk2(ev.y), pe2 = pk2(ev.z),
                       pe3 = pk2(ev.w), pe4 = pk2(e4);
    unsigned long long po0 = pk2(od.x), po1 = pk2(od.y), po2 = pk2(od.z), po3 = pk2(od.w);
    {
        const ulonglong2* w2 = reinterpret_cast<const ulonglong2*>(pw);
        ulonglong2 wa = w2[0], wb = w2[1];
        ffma2(acc[0], pe0, wa.x);  ffma2(acc[1], pe0, wa.y);
        ffma2(acc[2], pe0, wb.x);  ffma2(acc[3], pe0, wb.y);
        ffma2(acc[4], pe1, wa.x);  ffma2(acc[5], pe1, wa.y);
        ffma2(acc[6], pe1, wb.x);  ffma2(acc[7], pe1, wb.y);
        ffma2(acc[8], pe2, wa.x);  ffma2(acc[9], pe2, wa.y);
        ffma2(acc[10], pe2, wb.x); ffma2(acc[11], pe2, wb.y);
        ffma2(acc[12], pe3, wa.x); ffma2(acc[13], pe3, wa.y);
        ffma2(acc[14], pe3, wb.x); ffma2(acc[15], pe3, wb.y);
    }
    {
        const ulonglong2* w2 = reinterpret_cast<const ulonglong2*>(pw + 32);
        ulonglong2 wa = w2[0], wb = w2[1];
        ffma2(acc[0], po0, wa.x);  ffma2(acc[1], po0, wa.y);
        ffma2(acc[2], po0, wb.x);  ffma2(acc[3], po0, wb.y);
        ffma2(acc[4], po1, wa.x);  ffma2(acc[5], po1, wa.y);
        ffma2(acc[6], po1, wb.x);  ffma2(acc[7], po1, wb.y);
        ffma2(acc[8], po2, wa.x);  ffma2(acc[9], po2, wa.y);
        ffma2(acc[10], po2, wb.x); ffma2(acc[11], po2, wb.y);
        ffma2(acc[12], po3, wa.x); ffma2(acc[13], po3, wa.y);
        ffma2(acc[14], po3, wb.x); ffma2(acc[15], po3, wb.y);
    }
    {
        const ulonglong2* w2 = reinterpret_cast<const ulonglong2*>(pw + 64);
        ulonglong2 wa = w2[0], wb = w2[1];
        ffma2(acc[0], pe1, wa.x);  ffma2(acc[1], pe1, wa.y);
        ffma2(acc[2], pe1, wb.x);  ffma2(acc[3], pe1, wb.y);
        ffma2(acc[4], pe2, wa.x);  ffma2(acc[5], pe2, wa.y);
        ffma2(acc[6], pe2, wb.x);  ffma2(acc[7], pe2, wb.y);
        ffma2(acc[8], pe3, wa.x);  ffma2(acc[9], pe3, wa.y);
        ffma2(acc[10], pe3, wb.x); ffma2(acc[11], pe3, wb.y);
        ffma2(acc[12], pe4, wa.x); ffma2(acc[13], pe4, wa.y);
        ffma2(acc[14], pe4, wb.x); ffma2(acc[15], pe4, wb.y);
    }
}

template <int PLANE>
__device__ __forceinline__ void conv_store(const unsigned long long (&acc)[16],
                                           float* __restrict__ op,
                                           const float* __restrict__ bias,
                                           const float* __restrict__ bns,
                                           const float* __restrict__ bsh, int ocbase) {
#pragma unroll
    for (int j = 0; j < 4; j++) {
        int oc0 = ocbase + 2 * j;
        float bi0 = bias[oc0], sc0 = bns[oc0], sh0 = bsh[oc0];
        float bi1 = bias[oc0 + 1], sc1 = bns[oc0 + 1], sh1 = bsh[oc0 + 1];
        float4 v0, v1;
        v0.x = fmaxf(lo32(acc[0 + j]) + bi0, 0.f) * sc0 + sh0;
        v0.y = fmaxf(lo32(acc[4 + j]) + bi0, 0.f) * sc0 + sh0;
        v0.z = fmaxf(lo32(acc[8 + j]) + bi0, 0.f) * sc0 + sh0;
        v0.w = fmaxf(lo32(acc[12 + j]) + bi0, 0.f) * sc0 + sh0;
        v1.x = fmaxf(hi32(acc[0 + j]) + bi1, 0.f) * sc1 + sh1;
        v1.y = fmaxf(hi32(acc[4 + j]) + bi1, 0.f) * sc1 + sh1;
        v1.z = fmaxf(hi32(acc[8 + j]) + bi1, 0.f) * sc1 + sh1;
        v1.w = fmaxf(hi32(acc[12 + j]) + bi1, 0.f) * sc1 + sh1;
        *reinterpret_cast<float4*>(op + (size_t)(2 * j) * PLANE) = v0;
        *reinterpret_cast<float4*>(op + (size_t)(2 * j + 1) * PLANE) = v1;
    }
}

// ---------------------------------------------------------------------------
// conv1: 3 -> 32 ch, 255x255 -> 127x127 (row stride 128).  16x16 tile, 256 thr.
// Weights via uniform LDG (L1-resident, 3.4 KB).
// ---------------------------------------------------------------------------
__global__ void __launch_bounds__(256) conv1_kernel(const float* __restrict__ in,
                                                    const float* __restrict__ bias) {
    __shared__ __align__(16) float s_in[3 * 33 * 40];
    const int b = blockIdx.y;
    const int tx = blockIdx.x & 7, ty = blockIdx.x >> 3;
    const int ox0t = tx * 16, oy0 = ty * 16;
    const int ix0 = 2 * ox0t, iy0 = 2 * oy0;

    const float* inb = in + (size_t)b * 3 * 65025;
    int goff[5], soff[5];
#pragma unroll
    for (int k = 0; k < 5; k++) {
        int s = threadIdx.x + k * 256;
        s = min(s, 1088);
        int yy = s / 33, xx = s - yy * 33;
        int gy = min(iy0 + yy, 254), gx = min(ix0 + xx, 254);
        goff[k] = gy * 255 + gx;
        soff[k] = yy * 40 + ((xx & 1) ? 20 + (xx >> 1) : (xx >> 1));
    }
#pragma unroll
    for (int ic = 0; ic < 3; ic++) {
        float v[5];
#pragma unroll
        for (int k = 0; k < 5; k++) v[k] = inb[ic * 65025 + goff[k]];
#pragma unroll
        for (int k = 0; k < 5; k++) s_in[ic * 1320 + soff[k]] = v[k];
    }
    __syncthreads();

    const int xg = threadIdx.x & 3;
    const int y = (threadIdx.x >> 2) & 15;
    const int g = threadIdx.x >> 6;
    unsigned long long acc[16];
#pragma unroll
    for (int i = 0; i < 16; i++) acc[i] = 0ULL;

    const float* pw0 = g_wt1 + g * 8;
#pragma unroll
    for (int ic = 0; ic < 3; ic++) {
        const float* prb = s_in + ic * 1320 + (2 * y) * 40 + 4 * xg;
#pragma unroll
        for (int kh = 0; kh < 3; kh++) {
            const float* pr = prb + kh * 40;
            float4 ev = *reinterpret_cast<const float4*>(pr);
            float e4 = pr[4];
            float4 od = *reinterpret_cast<const float4*>(pr + 20);
            conv_row_taps(acc, ev, e4, od, pw0 + (ic * 9 + kh * 3) * 32);
        }
    }

    const int oy = oy0 + y;
    const int ox0 = ox0t + 4 * xg;
    if (oy < 127) {
        float* op = g_buf1 + ((size_t)b * 32 + g * 8) * (127 * 128) + (size_t)oy * 128 + ox0;
        conv_store<127 * 128>(acc, op, bias, g_bns, g_bsh, g * 8);
    }
}

// ---------------------------------------------------------------------------
// conv2..5: 32 -> 32 ch.  128 thr (xg4 x y8 x g4), 16x8 output tile,
// double-buffered 4-ic phases (one barrier/phase), pipelined 5-slot input
// fill, weights via uniform LDG.
// ---------------------------------------------------------------------------
template <int L, int IH, int IWS, int OH, int OWS, int TX>
__global__ void __launch_bounds__(128) conv32_kernel(const float* __restrict__ bias) {
    constexpr int IN_SLOTS = 4 * 17 * 9; // 612 float4 per phase
    constexpr int PHW = 4 * 680;         // words per buffer
    constexpr int DUMMY = 2 * PHW;
    __shared__ __align__(16) float smem[2 * PHW + 24];

    const int b = blockIdx.y;
    const int tx = blockIdx.x % TX, ty = blockIdx.x / TX;
    const int ox0t = tx * 16, oy0 = ty * 8;
    const int ix0 = 2 * ox0t, iy0 = 2 * oy0;
    const float* in = (L == 0) ? g_buf1 : (L == 1) ? g_buf2 : (L == 2) ? g_buf3 : g_buf4;
    float* out = (L == 0) ? g_buf2 : (L == 1) ? g_buf3 : (L == 2) ? g_buf4 : g_buf5;
    const float* inb = in + (size_t)b * 32 * IH * IWS;
    const float* wbase = g_wtl + L * 9216;

    const float* gp[5];
    int so[5];
#pragma unroll
    for (int k = 0; k < 5; k++) {
        int s = threadIdx.x + k * 128;
        if (s < IN_SLOTS) {
            int ic = s / 153, r = s - ic * 153;
            int yy = r / 9, xq = r - yy * 9;
            int gy = min(iy0 + yy, IH - 1);
            gp[k] = inb + ((size_t)ic * IH + gy) * IWS + ix0 + 4 * xq;
            so[k] = ic * 680 + yy * 40 + 2 * xq;
        } else {
            gp[k] = inb;
            so[k] = DUMMY;
        }
    }

    const int xg = threadIdx.x & 3;
    const int y = (threadIdx.x >> 2) & 7;
    const int g = threadIdx.x >> 5;
    unsigned long long acc[16];
#pragma unroll
    for (int i = 0; i < 16; i++) acc[i] = 0ULL;

    float4 pre[5];
#pragma unroll
    for (int k = 0; k < 5; k++) pre[k] = *reinterpret_cast<const float4*>(gp[k]);
#pragma unroll
    for (int k = 0; k < 5; k++) {
        float* bp = smem + ((so[k] == DUMMY) ? DUMMY : so[k]);
        *reinterpret_cast<float2*>(bp) = make_float2(pre[k].x, pre[k].z);
        *reinterpret_cast<float2*>(bp + 20) = make_float2(pre[k].y, pre[k].w);
    }

    for (int ph = 0; ph < 8; ph++) {
        __syncthreads();
        if (ph < 7) {
#pragma unroll
            for (int k = 0; k < 5; k++) {
                gp[k] += 4 * IH * IWS;
                pre[k] = *reinterpret_cast<const float4*>(gp[k]);
            }
        }
        const float* sb = smem + (ph & 1) * PHW;
        const float* wp = wbase + ph * (4 * 288) + g * 8;
#pragma unroll
        for (int ic = 0; ic < 4; ic++) {
            const float* prb = sb + ic * 680 + (2 * y) * 40 + 4 * xg;
            const float* pw1 = wp + ic * 288;
#pragma unroll
            for (int kh = 0; kh < 3; kh++) {
                const float* pr = prb + kh * 40;
                float4 ev = *reinterpret_cast<const float4*>(pr);
                float e4 = pr[4];
                float4 od = *reinterpret_cast<const float4*>(pr + 20);
                conv_row_taps(acc, ev, e4, od, pw1 + kh * 96);
            }
        }
        if (ph < 7) {
            float* db = smem + ((ph + 1) & 1) * PHW;
#pragma unroll
            for (int k = 0; k < 5; k++) {
                float* bp = (so[k] == DUMMY) ? (smem + DUMMY) : (db + so[k]);
                *reinterpret_cast<float2*>(bp) = make_float2(pre[k].x, pre[k].z);
                *reinterpret_cast<float2*>(bp + 20) = make_float2(pre[k].y, pre[k].w);
            }
        }
    }

    const int oy = oy0 + y;
    const int ox0 = ox0t + 4 * xg;
    if (oy < OH && ox0 < OWS) {
        const float* bns = g_bns + (L + 1) * 32;
        const float* bsh = g_bsh + (L + 1) * 32;
        float* op = out + ((size_t)b * 32 + g * 8) * (OH * OWS) + (size_t)oy * OWS + ox0;
        conv_store<OH * OWS>(acc, op, bias, bns, bsh, g * 8);
    }
}

// ---------------------------------------------------------------------------
// FC(1568->20 relu) -> FC(20->10) -> Thomas tridiagonal solve (fp64) -> a,b,c.
// ---------------------------------------------------------------------------
__global__ void __launch_bounds__(256) fc_kernel(const float* __restrict__ l1w,
                                                 const float* __restrict__ l1b,
                                                 const float* __restrict__ l2w,
                                                 const float* __restrict__ l2b) {
    __shared__ float s_y[1568];
    __shared__ float s_h1[20];
    __shared__ float s_ys[10];
    const int b = blockIdx.x;
    const float* yb = g_buf5 + (size_t)b * 32 * 7 * 8;
    for (int i = threadIdx.x; i < 1568; i += 256) {
        int oc = i / 49, r = i % 49;
        s_y[i] = yb[oc * 56 + (r / 7) * 8 + (r % 7)];
    }
    __syncthreads();

    const int warp = threadIdx.x >> 5, lane = threadIdx.x & 31;
    for (int j = warp; j < 20; j += 8) {
        float s = 0.f;
        const float* w = l1w + (size_t)j * 1568;
        for (int k = lane; k < 1568; k += 32) s += s_y[k] * w[k];
#pragma unroll
        for (int o = 16; o > 0; o >>= 1) s += __shfl_down_sync(0xffffffffu, s, o);
        if (lane == 0) s_h1[j] = fmaxf(s + l1b[j], 0.f);
    }
    __syncthreads();

    if (threadIdx.x < 10) {
        float s = l2b[threadIdx.x];
        const float* w = l2w + threadIdx.x * 20;
#pragma unroll
        for (int j = 0; j < 20; j++) s += s_h1[j] * w[j];
        s_ys[threadIdx.x] = s;
    }
    __syncthreads();

    if (threadIdx.x == 0) {
        const double h = 1.0 / 9.0;
        double ys[10];
#pragma unroll
        for (int i = 0; i < 10; i++) ys[i] = (double)s_ys[i];
        double d[8], cp[8];
        for (int i = 0; i < 8; i++)
            d[i] = (6.0 / (h * h)) * (ys[i + 2] - 2.0 * ys[i + 1] + ys[i]);
        cp[0] = 0.25;
        d[0] *= 0.25;
        for (int i = 1; i < 8; i++) {
            double m = 4.0 - cp[i - 1];
            cp[i] = 1.0 / m;
            d[i] = (d[i] - d[i - 1]) / m;
        }
        double M[10];
        M[0] = 0.0;
        M[9] = 0.0;
        M[8] = d[7];
        for (int i = 6; i >= 0; i--) M[i + 1] = d[i] - cp[i] * M[i + 2];
        float* cf = g_coef + b * 27;
        for (int i = 0; i < 9; i++) {
            cf[i] = (float)((M[i + 1] - M[i]) / (6.0 * h));
            cf[9 + i] = (float)(M[i] * 0.5);
            cf[18 + i] = (float)((ys[i + 1] - ys[i]) / h - (M[i + 1] + 2.0 * M[i]) * (h / 6.0));
        }
    }
}

// ---------------------------------------------------------------------------
// eval: fast bucket via x*9; exact __fdiv_rn fallback only within 1e-4 of a
// knot (true discrepancy <= 2e-7, so decisions match the reference).
// ---------------------------------------------------------------------------
__device__ __forceinline__ float evalpix(float x, const float* __restrict__ sc) {
    const float h = 1.0f / 9.0f;
    float tf = fminf(fmaxf(x * 9.0f, 0.f), 8.f);
    int xi = (int)tf;
    float fr = tf - (float)xi;
    if (fr < 1e-4f || fr > 0.9999f) {
        float te = fminf(fmaxf(__fdiv_rn(x, h), 0.f), 8.f);
        xi = (int)te;
    }
    float xf = x - (float)xi * h;
    return ((sc[xi] * xf + sc[9 + xi]) * xf + sc[18 + xi]) * xf;
}

__global__ void __launch_bounds__(256) eval_kernel(const float* __restrict__ in,
                                                   float* __restrict__ out) {
    __shared__ float s_c[27];
    const int b = blockIdx.y;
    if (threadIdx.x < 27) s_c[threadIdx.x] = g_coef[b * 27 + threadIdx.x];
    __syncthreads();
    const int N = 3 * 255 * 255;
    const float* ib = in + (size_t)b * N;
    float* ob = out + (size_t)b * N;
    const int mis = (4 - ((3 * b) & 3)) & 3;
    const int nv = (N - mis) >> 2;
    const float4* iv = reinterpret_cast<const float4*>(ib + mis);
    float4* ov = reinterpret_cast<float4*>(ob + mis);
    for (int v = blockIdx.x * 256 + threadIdx.x; v < nv; v += gridDim.x * 256) {
        float4 x = iv[v];
        float4 r;
        r.x = evalpix(x.x, s_c);
        r.y = evalpix(x.y, s_c);
        r.z = evalpix(x.z, s_c);
        r.w = evalpix(x.w, s_c);
        ov[v] = r;
    }
    const int tail = N - mis - 4 * nv;
    if (blockIdx.x == 0 && threadIdx.x < mis + tail) {
        int t = threadIdx.x;
        int i = (t < mis) ? t : (mis + 4 * nv + (t - mis));
        ob[i] = evalpix(ib[i], s_c);
    }
}

// ---------------------------------------------------------------------------
extern "C" void kernel_launch(void* const* d_in, const int* in_sizes, int n_in,
                              void* d_out, int out_size) {
    const float* batch = (const float*)d_in[0];
    const float* c1w = (const float*)d_in[1];
    const float* c1b = (const float*)d_in[2];
    const float* cw = (const float*)d_in[3];
    const float* cb = (const float*)d_in[4];
    const float* bng = (const float*)d_in[5];
    const float* bnb = (const float*)d_in[6];
    const float* bnm = (const float*)d_in[7];
    const float* bnv = (const float*)d_in[8];
    const float* l1w = (const float*)d_in[9];
    const float* l1b = (const float*)d_in[10];
    const float* l2w = (const float*)d_in[11];
    const float* l2b = (const float*)d_in[12];
    float* out = (float*)d_out;

    prep_kernel<<<64, 256>>>(c1w, cw, bng, bnb, bnm, bnv);
    conv1_kernel<<<dim3(64, 64), 256>>>(batch, c1b);
    conv32_kernel<0, 127, 128, 63, 64, 4><<<dim3(32, 64), 128>>>(cb + 0);  // 63x63, TY=8
    conv32_kernel<1, 63, 64, 31, 32, 2><<<dim3(8, 64), 128>>>(cb + 32);    // 31x31, TY=4
    conv32_kernel<2, 31, 32, 15, 16, 1><<<dim3(2, 64), 128>>>(cb + 64);    // 15x15, TY=2
    conv32_kernel<3, 15, 16, 7, 8, 1><<<dim3(1, 64), 128>>>(cb + 96);      // 7x7,   TY=1
    fc_kernel<<<64, 256>>>(l1w, l1b, l2w, l2b);
    eval_kernel<<<dim3(191, 64), 256>>>(batch, out);
}

// round 7
// speedup vs baseline: 1.6896x; 1.6896x over previous
#include <cuda_runtime.h>
#include <cstdint>

// ---------------------------------------------------------------------------
// NeuralSpline R5 (second resubmit; two prior rounds were broker/container
// infra failures with no harness output; source audited for OOB/hangs):
// R3 compute economics (smem weights) + 128-thr 16x8-tile conv32 for 2x grid
// parallelism.
// ---------------------------------------------------------------------------

#define EPSF 1e-5f

static __device__ float g_buf1[64 * 32 * 127 * 128 + 64];
static __device__ float g_buf2[64 * 32 * 63 * 64 + 64];
static __device__ float g_buf3[64 * 32 * 31 * 32 + 64];
static __device__ float g_buf4[64 * 32 * 15 * 16 + 64];
static __device__ float g_buf5[64 * 32 * 7 * 8 + 64];
static __device__ float g_wt1[27 * 32];
static __device__ float g_wtl[4 * 288 * 32];
static __device__ float g_bns[5 * 32];
static __device__ float g_bsh[5 * 32];
static __device__ float g_coef[64 * 27];

// ---- packed f32x2 helpers ---------------------------------------------------
__device__ __forceinline__ unsigned long long pk2(float x) {
    unsigned long long r;
    unsigned u = __float_as_uint(x);
    asm("mov.b64 %0, {%1, %1};" : "=l"(r) : "r"(u));
    return r;
}
__device__ __forceinline__ void ffma2(unsigned long long& a, unsigned long long x,
                                      unsigned long long w) {
    asm("fma.rn.f32x2 %0, %1, %2, %0;" : "+l"(a) : "l"(x), "l"(w));
}
__device__ __forceinline__ float lo32(unsigned long long v) {
    return __uint_as_float((unsigned)(v & 0xffffffffULL));
}
__device__ __forceinline__ float hi32(unsigned long long v) {
    return __uint_as_float((unsigned)(v >> 32));
}

// ---------------------------------------------------------------------------
__global__ void prep_kernel(const float* __restrict__ c1w, const float* __restrict__ cw,
                            const float* __restrict__ bng, const float* __restrict__ bnb,
                            const float* __restrict__ bnm, const float* __restrict__ bnv) {
    const int stride = gridDim.x * blockDim.x;
    const int t0 = blockIdx.x * blockDim.x + threadIdx.x;
    for (int i = t0; i < 5 * 32; i += stride) {
        float inv = bng[i] * rsqrtf(bnv[i] + EPSF);
        g_bns[i] = inv;
        g_bsh[i] = bnb[i] - bnm[i] * inv;
    }
    for (int i = t0; i < 27 * 32; i += stride) {
        int oc = i / 27, r = i % 27;
        g_wt1[r * 32 + oc] = c1w[i];
    }
    for (int i = t0; i < 4 * 32 * 288; i += stride) {
        int l = i / 9216, rem = i % 9216;
        int oc = rem / 288, r = rem % 288;
        g_wtl[l * 9216 + r * 32 + oc] = cw[i];
    }
}

// 48 FFMA2 for one (ic,kh) row unit; weights via broadcast LDS.128 from smem.
__device__ __forceinline__ void conv_row_taps(unsigned long long (&acc)[16],
                                              const float4 ev, const float e4,
                                              const float4 od,
                                              const float* __restrict__ pw) {
    unsigned long long pe0 = pk2(ev.x), pe1 = pk2(ev.y), pe2 = pk2(ev.z),
                       pe3 = pk2(ev.w), pe4 = pk2(e4);
    unsigned long long po0 = pk2(od.x), po1 = pk2(od.y), po2 = pk2(od.z), po3 = pk2(od.w);
    {
        const ulonglong2* w2 = reinterpret_cast<const ulonglong2*>(pw);
        ulonglong2 wa = w2[0], wb = w2[1];
        ffma2(acc[0], pe0, wa.x);  ffma2(acc[1], pe0, wa.y);
        ffma2(acc[2], pe0, wb.x);  ffma2(acc[3], pe0, wb.y);
        ffma2(acc[4], pe1, wa.x);  ffma2(acc[5], pe1, wa.y);
        ffma2(acc[6], pe1, wb.x);  ffma2(acc[7], pe1, wb.y);
        ffma2(acc[8], pe2, wa.x);  ffma2(acc[9], pe2, wa.y);
        ffma2(acc[10], pe2, wb.x); ffma2(acc[11], pe2, wb.y);
        ffma2(acc[12], pe3, wa.x); ffma2(acc[13], pe3, wa.y);
        ffma2(acc[14], pe3, wb.x); ffma2(acc[15], pe3, wb.y);
    }
    {
        const ulonglong2* w2 = reinterpret_cast<const ulonglong2*>(pw + 32);
        ulonglong2 wa = w2[0], wb = w2[1];
        ffma2(acc[0], po0, wa.x);  ffma2(acc[1], po0, wa.y);
        ffma2(acc[2], po0, wb.x);  ffma2(acc[3], po0, wb.y);
        ffma2(acc[4], po1, wa.x);  ffma2(acc[5], po1, wa.y);
        ffma2(acc[6], po1, wb.x);  ffma2(acc[7], po1, wb.y);
        ffma2(acc[8], po2, wa.x);  ffma2(acc[9], po2, wa.y);
        ffma2(acc[10], po2, wb.x); ffma2(acc[11], po2, wb.y);
        ffma2(acc[12], po3, wa.x); ffma2(acc[13], po3, wa.y);
        ffma2(acc[14], po3, wb.x); ffma2(acc[15], po3, wb.y);
    }
    {
        const ulonglong2* w2 = reinterpret_cast<const ulonglong2*>(pw + 64);
        ulonglong2 wa = w2[0], wb = w2[1];
        ffma2(acc[0], pe1, wa.x);  ffma2(acc[1], pe1, wa.y);
        ffma2(acc[2], pe1, wb.x);  ffma2(acc[3], pe1, wb.y);
        ffma2(acc[4], pe2, wa.x);  ffma2(acc[5], pe2, wa.y);
        ffma2(acc[6], pe2, wb.x);  ffma2(acc[7], pe2, wb.y);
        ffma2(acc[8], pe3, wa.x);  ffma2(acc[9], pe3, wa.y);
        ffma2(acc[10], pe3, wb.x); ffma2(acc[11], pe3, wb.y);
        ffma2(acc[12], pe4, wa.x); ffma2(acc[13], pe4, wa.y);
        ffma2(acc[14], pe4, wb.x); ffma2(acc[15], pe4, wb.y);
    }
}

template <int PLANE>
__device__ __forceinline__ void conv_store(const unsigned long long (&acc)[16],
                                           float* __restrict__ op,
                                           const float* __restrict__ bias,
                                           const float* __restrict__ bns,
                                           const float* __restrict__ bsh, int ocbase) {
#pragma unroll
    for (int j = 0; j < 4; j++) {
        int oc0 = ocbase + 2 * j;
        float bi0 = bias[oc0], sc0 = bns[oc0], sh0 = bsh[oc0];
        float bi1 = bias[oc0 + 1], sc1 = bns[oc0 + 1], sh1 = bsh[oc0 + 1];
        float4 v0, v1;
        v0.x = fmaxf(lo32(acc[0 + j]) + bi0, 0.f) * sc0 + sh0;
        v0.y = fmaxf(lo32(acc[4 + j]) + bi0, 0.f) * sc0 + sh0;
        v0.z = fmaxf(lo32(acc[8 + j]) + bi0, 0.f) * sc0 + sh0;
        v0.w = fmaxf(lo32(acc[12 + j]) + bi0, 0.f) * sc0 + sh0;
        v1.x = fmaxf(hi32(acc[0 + j]) + bi1, 0.f) * sc1 + sh1;
        v1.y = fmaxf(hi32(acc[4 + j]) + bi1, 0.f) * sc1 + sh1;
        v1.z = fmaxf(hi32(acc[8 + j]) + bi1, 0.f) * sc1 + sh1;
        v1.w = fmaxf(hi32(acc[12 + j]) + bi1, 0.f) * sc1 + sh1;
        *reinterpret_cast<float4*>(op + (size_t)(2 * j) * PLANE) = v0;
        *reinterpret_cast<float4*>(op + (size_t)(2 * j + 1) * PLANE) = v1;
    }
}

// ---------------------------------------------------------------------------
// conv1: 3 -> 32 ch, 255x255 -> 127x127.  16x16 tile, 256 thr (R3 version).
// ---------------------------------------------------------------------------
__global__ void __launch_bounds__(256) conv1_kernel(const float* __restrict__ in,
                                                    const float* __restrict__ bias) {
    __shared__ __align__(16) float s_in[3 * 33 * 40];
    __shared__ __align__(16) float s_w[27 * 32];
    const int b = blockIdx.y;
    const int tx = blockIdx.x & 7, ty = blockIdx.x >> 3;
    const int ox0t = tx * 16, oy0 = ty * 16;
    const int ix0 = 2 * ox0t, iy0 = 2 * oy0;

    if (threadIdx.x < 216)
        reinterpret_cast<float4*>(s_w)[threadIdx.x] =
            reinterpret_cast<const float4*>(g_wt1)[threadIdx.x];

    const float* inb = in + (size_t)b * 3 * 65025;
    int goff[5], soff[5];
#pragma unroll
    for (int k = 0; k < 5; k++) {
        int s = threadIdx.x + k * 256;
        s = min(s, 1088);
        int yy = s / 33, xx = s - yy * 33;
        int gy = min(iy0 + yy, 254), gx = min(ix0 + xx, 254);
        goff[k] = gy * 255 + gx;
        soff[k] = yy * 40 + ((xx & 1) ? 20 + (xx >> 1) : (xx >> 1));
    }
#pragma unroll
    for (int ic = 0; ic < 3; ic++) {
        float v[5];
#pragma unroll
        for (int k = 0; k < 5; k++) v[k] = inb[ic * 65025 + goff[k]];
#pragma unroll
        for (int k = 0; k < 5; k++) s_in[ic * 1320 + soff[k]] = v[k];
    }
    __syncthreads();

    const int xg = threadIdx.x & 3;
    const int y = (threadIdx.x >> 2) & 15;
    const int g = threadIdx.x >> 6;
    unsigned long long acc[16];
#pragma unroll
    for (int i = 0; i < 16; i++) acc[i] = 0ULL;

    const float* pw0 = s_w + g * 8;
#pragma unroll
    for (int ic = 0; ic < 3; ic++) {
        const float* prb = s_in + ic * 1320 + (2 * y) * 40 + 4 * xg;
#pragma unroll
        for (int kh = 0; kh < 3; kh++) {
            const float* pr = prb + kh * 40;
            float4 ev = *reinterpret_cast<const float4*>(pr);
            float e4 = pr[4];
            float4 od = *reinterpret_cast<const float4*>(pr + 20);
            conv_row_taps(acc, ev, e4, od, pw0 + (ic * 9 + kh * 3) * 32);
        }
    }

    const int oy = oy0 + y;
    const int ox0 = ox0t + 4 * xg;
    if (oy < 127) {
        float* op = g_buf1 + ((size_t)b * 32 + g * 8) * (127 * 128) + (size_t)oy * 128 + ox0;
        conv_store<127 * 128>(acc, op, bias, g_bns, g_bsh, g * 8);
    }
}

// ---------------------------------------------------------------------------
// conv2..5: 32 -> 32 ch.  128 thr (xg4 x y8 x g4), 16x8 tile, 4-ic x 8 phases,
// single smem buffer + pipelined 8-slot fill (5 input + 3 weight), smem
// weights (broadcast LDS).
// ---------------------------------------------------------------------------
template <int L, int IH, int IWS, int OH, int OWS, int TX>
__global__ void __launch_bounds__(128) conv32_kernel(const float* __restrict__ bias) {
    constexpr int IN_SLOTS = 4 * 17 * 9;       // 612 float4 per phase
    constexpr int W_SLOTS = 288;               // 1152 floats / 4
    constexpr int SW_FL = 4 * 680;             // 2720: s_w float offset
    constexpr unsigned SW_B = SW_FL * 4u;
    constexpr int DUMMY_FL = SW_FL + 1152;     // 3872
    __shared__ __align__(16) float smem[DUMMY_FL + 16];
    char* const smb = reinterpret_cast<char*>(smem);
    float* const s_in = smem;
    float* const s_w = smem + SW_FL;

    const int b = blockIdx.y;
    const int tx = blockIdx.x % TX, ty = blockIdx.x / TX;
    const int ox0t = tx * 16, oy0 = ty * 8;
    const int ix0 = 2 * ox0t, iy0 = 2 * oy0;
    const float* in = (L == 0) ? g_buf1 : (L == 1) ? g_buf2 : (L == 2) ? g_buf3 : g_buf4;
    float* out = (L == 0) ? g_buf2 : (L == 1) ? g_buf3 : (L == 2) ? g_buf4 : g_buf5;
    const float* inb = in + (size_t)b * 32 * IH * IWS;
    const float* wt = g_wtl + L * 9216;

    // 8 fill slots: 5 input + 3 weight, all pipelined
    const float* gp[8];
    unsigned sm1[8], sm2[8];
    bool isw[8];
#pragma unroll
    for (int k = 0; k < 8; k++) {
        if (k < 5) {
            int s = threadIdx.x + k * 128;
            if (s < IN_SLOTS) {
                int ic = s / 153, r = s - ic * 153;
                int yy = r / 9, xq = r - yy * 9;
                int gy = min(iy0 + yy, IH - 1);
                gp[k] = inb + ((size_t)ic * IH + gy) * IWS + ix0 + 4 * xq;
                unsigned so = (unsigned)(ic * 680 + yy * 40 + 2 * xq) * 4u;
                sm1[k] = so;
                sm2[k] = so + 80;
                isw[k] = false;
            } else {
                gp[k] = inb;
                sm1[k] = DUMMY_FL * 4u;
                sm2[k] = sm1[k] + 8;
                isw[k] = false;
            }
        } else {
            int idx = threadIdx.x + (k - 5) * 128;
            if (idx < W_SLOTS) {
                gp[k] = wt + idx * 4;
                unsigned so = SW_B + (unsigned)idx * 16u;
                sm1[k] = so;
                sm2[k] = so + 8;
                isw[k] = true;
            } else {
                gp[k] = wt;
                sm1[k] = DUMMY_FL * 4u;
                sm2[k] = sm1[k] + 8;
                isw[k] = true;
            }
        }
    }

    const int xg = threadIdx.x & 3;
    const int y = (threadIdx.x >> 2) & 7;
    const int g = threadIdx.x >> 5;
    unsigned long long acc[16];
#pragma unroll
    for (int i = 0; i < 16; i++) acc[i] = 0ULL;

    float4 pre[8];
#pragma unroll
    for (int k = 0; k < 8; k++) pre[k] = *reinterpret_cast<const float4*>(gp[k]);

    for (int ph = 0; ph < 8; ph++) {
        if (ph) __syncthreads(); // prev compute done before overwrite
#pragma unroll
        for (int k = 0; k < 8; k++) {
            float4 v = pre[k];
            float a1 = isw[k] ? v.y : v.z;
            float a2 = isw[k] ? v.z : v.y;
            *reinterpret_cast<float2*>(smb + sm1[k]) = make_float2(v.x, a1);
            *reinterpret_cast<float2*>(smb + sm2[k]) = make_float2(a2, v.w);
        }
        __syncthreads();
        if (ph < 7) {
#pragma unroll
            for (int k = 0; k < 8; k++) {
                gp[k] += isw[k] ? 1152 : 4 * IH * IWS;
                pre[k] = *reinterpret_cast<const float4*>(gp[k]);
            }
        }
        const float* pw0 = s_w + g * 8;
#pragma unroll
        for (int ic = 0; ic < 4; ic++) {
            const float* prb = s_in + ic * 680 + (2 * y) * 40 + 4 * xg;
            const float* pw1 = pw0 + ic * 288;
#pragma unroll
            for (int kh = 0; kh < 3; kh++) {
                const float* pr = prb + kh * 40;
                float4 ev = *reinterpret_cast<const float4*>(pr);
                float e4 = pr[4];
                float4 od = *reinterpret_cast<const float4*>(pr + 20);
                conv_row_taps(acc, ev, e4, od, pw1 + kh * 96);
            }
        }
    }

    const int oy = oy0 + y;
    const int ox0 = ox0t + 4 * xg;
    if (oy < OH && ox0 < OWS) {
        const float* bns = g_bns + (L + 1) * 32;
        const float* bsh = g_bsh + (L + 1) * 32;
        float* op = out + ((size_t)b * 32 + g * 8) * (OH * OWS) + (size_t)oy * OWS + ox0;
        conv_store<OH * OWS>(acc, op, bias, bns, bsh, g * 8);
    }
}

// ---------------------------------------------------------------------------
// FC(1568->20 relu) -> FC(20->10) -> Thomas tridiagonal solve (fp64) -> a,b,c.
// ---------------------------------------------------------------------------
__global__ void __launch_bounds__(256) fc_kernel(const float* __restrict__ l1w,
                                                 const float* __restrict__ l1b,
                                                 const float* __restrict__ l2w,
                                                 const float* __restrict__ l2b) {
    __shared__ float s_y[1568];
    __shared__ float s_h1[20];
    __shared__ float s_ys[10];
    const int b = blockIdx.x;
    const float* yb = g_buf5 + (size_t)b * 32 * 7 * 8;
    for (int i = threadIdx.x; i < 1568; i += 256) {
        int oc = i / 49, r = i % 49;
        s_y[i] = yb[oc * 56 + (r / 7) * 8 + (r % 7)];
    }
    __syncthreads();

    const int warp = threadIdx.x >> 5, lane = threadIdx.x & 31;
    for (int j = warp; j < 20; j += 8) {
        float s = 0.f;
        const float* w = l1w + (size_t)j * 1568;
        for (int k = lane; k < 1568; k += 32) s += s_y[k] * w[k];
#pragma unroll
        for (int o = 16; o > 0; o >>= 1) s += __shfl_down_sync(0xffffffffu, s, o);
        if (lane == 0) s_h1[j] = fmaxf(s + l1b[j], 0.f);
    }
    __syncthreads();

    if (threadIdx.x < 10) {
        float s = l2b[threadIdx.x];
        const float* w = l2w + threadIdx.x * 20;
#pragma unroll
        for (int j = 0; j < 20; j++) s += s_h1[j] * w[j];
        s_ys[threadIdx.x] = s;
    }
    __syncthreads();

    if (threadIdx.x == 0) {
        const double h = 1.0 / 9.0;
        double ys[10];
#pragma unroll
        for (int i = 0; i < 10; i++) ys[i] = (double)s_ys[i];
        double d[8], cp[8];
        for (int i = 0; i < 8; i++)
            d[i] = (6.0 / (h * h)) * (ys[i + 2] - 2.0 * ys[i + 1] + ys[i]);
        cp[0] = 0.25;
        d[0] *= 0.25;
        for (int i = 1; i < 8; i++) {
            double m = 4.0 - cp[i - 1];
            cp[i] = 1.0 / m;
            d[i] = (d[i] - d[i - 1]) / m;
        }
        double M[10];
        M[0] = 0.0;
        M[9] = 0.0;
        M[8] = d[7];
        for (int i = 6; i >= 0; i--) M[i + 1] = d[i] - cp[i] * M[i + 2];
        float* cf = g_coef + b * 27;
        for (int i = 0; i < 9; i++) {
            cf[i] = (float)((M[i + 1] - M[i]) / (6.0 * h));
            cf[9 + i] = (float)(M[i] * 0.5);
            cf[18 + i] = (float)((ys[i + 1] - ys[i]) / h - (M[i + 1] + 2.0 * M[i]) * (h / 6.0));
        }
    }
}

// ---------------------------------------------------------------------------
// eval: fast bucket via x*9; exact __fdiv_rn fallback only near knots.
// ---------------------------------------------------------------------------
__device__ __forceinline__ float evalpix(float x, const float* __restrict__ sc) {
    const float h = 1.0f / 9.0f;
    float tf = fminf(fmaxf(x * 9.0f, 0.f), 8.f);
    int xi = (int)tf;
    float fr = tf - (float)xi;
    if (fr < 1e-4f || fr > 0.9999f) {
        float te = fminf(fmaxf(__fdiv_rn(x, h), 0.f), 8.f);
        xi = (int)te;
    }
    float xf = x - (float)xi * h;
    return ((sc[xi] * xf + sc[9 + xi]) * xf + sc[18 + xi]) * xf;
}

__global__ void __launch_bounds__(256) eval_kernel(const float* __restrict__ in,
                                                   float* __restrict__ out) {
    __shared__ float s_c[27];
    const int b = blockIdx.y;
    if (threadIdx.x < 27) s_c[threadIdx.x] = g_coef[b * 27 + threadIdx.x];
    __syncthreads();
    const int N = 3 * 255 * 255;
    const float* ib = in + (size_t)b * N;
    float* ob = out + (size_t)b * N;
    const int mis = (4 - ((3 * b) & 3)) & 3;
    const int nv = (N - mis) >> 2;
    const float4* iv = reinterpret_cast<const float4*>(ib + mis);
    float4* ov = reinterpret_cast<float4*>(ob + mis);
    for (int v = blockIdx.x * 256 + threadIdx.x; v < nv; v += gridDim.x * 256) {
        float4 x = iv[v];
        float4 r;
        r.x = evalpix(x.x, s_c);
        r.y = evalpix(x.y, s_c);
        r.z = evalpix(x.z, s_c);
        r.w = evalpix(x.w, s_c);
        ov[v] = r;
    }
    const int tail = N - mis - 4 * nv;
    if (blockIdx.x == 0 && threadIdx.x < mis + tail) {
        int t = threadIdx.x;
        int i = (t < mis) ? t : (mis + 4 * nv + (t - mis));
        ob[i] = evalpix(ib[i], s_c);
    }
}

// ---------------------------------------------------------------------------
extern "C" void kernel_launch(void* const* d_in, const int* in_sizes, int n_in,
                              void* d_out, int out_size) {
    const float* batch = (const float*)d_in[0];
    const float* c1w = (const float*)d_in[1];
    const float* c1b = (const float*)d_in[2];
    const float* cw = (const float*)d_in[3];
    const float* cb = (const float*)d_in[4];
    const float* bng = (const float*)d_in[5];
    const float* bnb = (const float*)d_in[6];
    const float* bnm = (const float*)d_in[7];
    const float* bnv = (const float*)d_in[8];
    const float* l1w = (const float*)d_in[9];
    const float* l1b = (const float*)d_in[10];
    const float* l2w = (const float*)d_in[11];
    const float* l2b = (const float*)d_in[12];
    float* out = (float*)d_out;

    prep_kernel<<<64, 256>>>(c1w, cw, bng, bnb, bnm, bnv);
    conv1_kernel<<<dim3(64, 64), 256>>>(batch, c1b);
    conv32_kernel<0, 127, 128, 63, 64, 4><<<dim3(32, 64), 128>>>(cb + 0);
    conv32_kernel<1, 63, 64, 31, 32, 2><<<dim3(8, 64), 128>>>(cb + 32);
    conv32_kernel<2, 31, 32, 15, 16, 1><<<dim3(2, 64), 128>>>(cb + 64);
    conv32_kernel<3, 15, 16, 7, 8, 1><<<dim3(1, 64), 128>>>(cb + 96);
    fc_kernel<<<64, 256>>>(l1w, l1b, l2w, l2b);
    eval_kernel<<<dim3(191, 64), 256>>>(batch, out);
}

// round 9
// speedup vs baseline: 1.7695x; 1.0472x over previous
#include <cuda_runtime.h>
#include <cstdint>

// ---------------------------------------------------------------------------
// NeuralSpline R9 = R8 + restored `ox0 < OWS` store guard (R8's dropped guard
// let padding lanes of conv32<3> clobber valid odd-half/next-row data in buf5
// -> rel_err 0.447).  Even/odd-split buffers + cp.async double-buffered fill.
// ---------------------------------------------------------------------------

#define EPSF 1e-5f

// Buffers: per row [even half | odd half], row stride = old padded width.
static __device__ __align__(16) float g_buf1[64 * 32 * 127 * 128 + 64];
static __device__ __align__(16) float g_buf2[64 * 32 * 63 * 64 + 64];
static __device__ __align__(16) float g_buf3[64 * 32 * 31 * 32 + 64];
static __device__ __align__(16) float g_buf4[64 * 32 * 15 * 16 + 64];
static __device__ __align__(16) float g_buf5[64 * 32 * 7 * 8 + 64];
static __device__ __align__(16) float g_wt1[27 * 32];
static __device__ __align__(16) float g_wtl[4 * 288 * 32];
static __device__ float g_bns[5 * 32];
static __device__ float g_bsh[5 * 32];
static __device__ float g_coef[64 * 27];

// ---- packed f32x2 helpers ---------------------------------------------------
__device__ __forceinline__ unsigned long long pk2(float x) {
    unsigned long long r;
    unsigned u = __float_as_uint(x);
    asm("mov.b64 %0, {%1, %1};" : "=l"(r) : "r"(u));
    return r;
}
__device__ __forceinline__ void ffma2(unsigned long long& a, unsigned long long x,
                                      unsigned long long w) {
    asm("fma.rn.f32x2 %0, %1, %2, %0;" : "+l"(a) : "l"(x), "l"(w));
}
__device__ __forceinline__ float lo32(unsigned long long v) {
    return __uint_as_float((unsigned)(v & 0xffffffffULL));
}
__device__ __forceinline__ float hi32(unsigned long long v) {
    return __uint_as_float((unsigned)(v >> 32));
}
__device__ __forceinline__ uint32_t smem_u32(const void* p) {
    uint32_t a;
    asm("{ .reg .u64 t; cvta.to.shared.u64 t, %1; cvt.u32.u64 %0, t; }" : "=r"(a) : "l"(p));
    return a;
}
__device__ __forceinline__ void cp16(uint32_t dst, const void* src) {
    asm volatile("cp.async.cg.shared.global [%0], [%1], 16;" :: "r"(dst), "l"(src));
}

// ---------------------------------------------------------------------------
__global__ void prep_kernel(const float* __restrict__ c1w, const float* __restrict__ cw,
                            const float* __restrict__ bng, const float* __restrict__ bnb,
                            const float* __restrict__ bnm, const float* __restrict__ bnv) {
    const int stride = gridDim.x * blockDim.x;
    const int t0 = blockIdx.x * blockDim.x + threadIdx.x;
    for (int i = t0; i < 5 * 32; i += stride) {
        float inv = bng[i] * rsqrtf(bnv[i] + EPSF);
        g_bns[i] = inv;
        g_bsh[i] = bnb[i] - bnm[i] * inv;
    }
    for (int i = t0; i < 27 * 32; i += stride) {
        int oc = i / 27, r = i % 27;
        g_wt1[r * 32 + oc] = c1w[i];
    }
    for (int i = t0; i < 4 * 32 * 288; i += stride) {
        int l = i / 9216, rem = i % 9216;
        int oc = rem / 288, r = rem % 288;
        g_wtl[l * 9216 + r * 32 + oc] = cw[i];
    }
}

// 48 FFMA2 per (ic,kh) row unit; weights via broadcast LDS.128.
__device__ __forceinline__ void conv_row_taps(unsigned long long (&acc)[16],
                                              const float4 ev, const float e4,
                                              const float4 od,
                                              const float* __restrict__ pw) {
    unsigned long long pe0 = pk2(ev.x), pe1 = pk2(ev.y), pe2 = pk2(ev.z),
                       pe3 = pk2(ev.w), pe4 = pk2(e4);
    unsigned long long po0 = pk2(od.x), po1 = pk2(od.y), po2 = pk2(od.z), po3 = pk2(od.w);
    {
        const ulonglong2* w2 = reinterpret_cast<const ulonglong2*>(pw);
        ulonglong2 wa = w2[0], wb = w2[1];
        ffma2(acc[0], pe0, wa.x);  ffma2(acc[1], pe0, wa.y);
        ffma2(acc[2], pe0, wb.x);  ffma2(acc[3], pe0, wb.y);
        ffma2(acc[4], pe1, wa.x);  ffma2(acc[5], pe1, wa.y);
        ffma2(acc[6], pe1, wb.x);  ffma2(acc[7], pe1, wb.y);
        ffma2(acc[8], pe2, wa.x);  ffma2(acc[9], pe2, wa.y);
        ffma2(acc[10], pe2, wb.x); ffma2(acc[11], pe2, wb.y);
        ffma2(acc[12], pe3, wa.x); ffma2(acc[13], pe3, wa.y);
        ffma2(acc[14], pe3, wb.x); ffma2(acc[15], pe3, wb.y);
    }
    {
        const ulonglong2* w2 = reinterpret_cast<const ulonglong2*>(pw + 32);
        ulonglong2 wa = w2[0], wb = w2[1];
        ffma2(acc[0], po0, wa.x);  ffma2(acc[1], po0, wa.y);
        ffma2(acc[2], po0, wb.x);  ffma2(acc[3], po0, wb.y);
        ffma2(acc[4], po1, wa.x);  ffma2(acc[5], po1, wa.y);
        ffma2(acc[6], po1, wb.x);  ffma2(acc[7], po1, wb.y);
        ffma2(acc[8], po2, wa.x);  ffma2(acc[9], po2, wa.y);
        ffma2(acc[10], po2, wb.x); ffma2(acc[11], po2, wb.y);
        ffma2(acc[12], po3, wa.x); ffma2(acc[13], po3, wa.y);
        ffma2(acc[14], po3, wb.x); ffma2(acc[15], po3, wb.y);
    }
    {
        const ulonglong2* w2 = reinterpret_cast<const ulonglong2*>(pw + 64);
        ulonglong2 wa = w2[0], wb = w2[1];
        ffma2(acc[0], pe1, wa.x);  ffma2(acc[1], pe1, wa.y);
        ffma2(acc[2], pe1, wb.x);  ffma2(acc[3], pe1, wb.y);
        ffma2(acc[4], pe2, wa.x);  ffma2(acc[5], pe2, wa.y);
        ffma2(acc[6], pe2, wb.x);  ffma2(acc[7], pe2, wb.y);
        ffma2(acc[8], pe3, wa.x);  ffma2(acc[9], pe3, wa.y);
        ffma2(acc[10], pe3, wb.x); ffma2(acc[11], pe3, wb.y);
        ffma2(acc[12], pe4, wa.x); ffma2(acc[13], pe4, wa.y);
        ffma2(acc[14], pe4, wb.x); ffma2(acc[15], pe4, wb.y);
    }
}

// Epilogue: bias+relu+BN; write even/odd-split rows (2x STG.64 per oc).
template <int PLANE, int OE>
__device__ __forceinline__ void conv_store(const unsigned long long (&acc)[16],
                                           float* __restrict__ op,
                                           const float* __restrict__ bias,
                                           const float* __restrict__ bns,
                                           const float* __restrict__ bsh, int ocbase) {
#pragma unroll
    for (int j = 0; j < 4; j++) {
        int oc0 = ocbase + 2 * j;
        float bi0 = bias[oc0], sc0 = bns[oc0], sh0 = bsh[oc0];
        float bi1 = bias[oc0 + 1], sc1 = bns[oc0 + 1], sh1 = bsh[oc0 + 1];
        float t0 = fmaxf(lo32(acc[0 + j]) + bi0, 0.f) * sc0 + sh0;  // x+0 (even)
        float t1 = fmaxf(lo32(acc[4 + j]) + bi0, 0.f) * sc0 + sh0;  // x+1 (odd)
        float t2 = fmaxf(lo32(acc[8 + j]) + bi0, 0.f) * sc0 + sh0;  // x+2 (even)
        float t3 = fmaxf(lo32(acc[12 + j]) + bi0, 0.f) * sc0 + sh0; // x+3 (odd)
        float u0 = fmaxf(hi32(acc[0 + j]) + bi1, 0.f) * sc1 + sh1;
        float u1 = fmaxf(hi32(acc[4 + j]) + bi1, 0.f) * sc1 + sh1;
        float u2 = fmaxf(hi32(acc[8 + j]) + bi1, 0.f) * sc1 + sh1;
        float u3 = fmaxf(hi32(acc[12 + j]) + bi1, 0.f) * sc1 + sh1;
        float* p0 = op + (size_t)(2 * j) * PLANE;
        float* p1 = op + (size_t)(2 * j + 1) * PLANE;
        *reinterpret_cast<float2*>(p0) = make_float2(t0, t2);
        *reinterpret_cast<float2*>(p0 + OE) = make_float2(t1, t3);
        *reinterpret_cast<float2*>(p1) = make_float2(u0, u2);
        *reinterpret_cast<float2*>(p1 + OE) = make_float2(u1, u3);
    }
}

// ---------------------------------------------------------------------------
// conv1: 3 -> 32 ch, 255x255 -> 127 x (64e|63o).  16x16 tile, 256 thr.
// ---------------------------------------------------------------------------
__global__ void __launch_bounds__(256) conv1_kernel(const float* __restrict__ in,
                                                    const float* __restrict__ bias) {
    __shared__ __align__(16) float s_in[3 * 33 * 40];
    __shared__ __align__(16) float s_w[27 * 32];
    const int b = blockIdx.y;
    const int tx = blockIdx.x & 7, ty = blockIdx.x >> 3;
    const int ox0t = tx * 16, oy0 = ty * 16;
    const int ix0 = 2 * ox0t, iy0 = 2 * oy0;

    if (threadIdx.x < 216)
        reinterpret_cast<float4*>(s_w)[threadIdx.x] =
            reinterpret_cast<const float4*>(g_wt1)[threadIdx.x];

    const float* inb = in + (size_t)b * 3 * 65025;
    int goff[5], soff[5];
#pragma unroll
    for (int k = 0; k < 5; k++) {
        int s = threadIdx.x + k * 256;
        s = min(s, 1088);
        int yy = s / 33, xx = s - yy * 33;
        int gy = min(iy0 + yy, 254), gx = min(ix0 + xx, 254);
        goff[k] = gy * 255 + gx;
        soff[k] = yy * 40 + ((xx & 1) ? 20 + (xx >> 1) : (xx >> 1));
    }
#pragma unroll
    for (int ic = 0; ic < 3; ic++) {
        float v[5];
#pragma unroll
        for (int k = 0; k < 5; k++) v[k] = inb[ic * 65025 + goff[k]];
#pragma unroll
        for (int k = 0; k < 5; k++) s_in[ic * 1320 + soff[k]] = v[k];
    }
    __syncthreads();

    const int xg = threadIdx.x & 3;
    const int y = (threadIdx.x >> 2) & 15;
    const int g = threadIdx.x >> 6;
    unsigned long long acc[16];
#pragma unroll
    for (int i = 0; i < 16; i++) acc[i] = 0ULL;

    const float* pw0 = s_w + g * 8;
#pragma unroll
    for (int ic = 0; ic < 3; ic++) {
        const float* prb = s_in + ic * 1320 + (2 * y) * 40 + 4 * xg;
#pragma unroll
        for (int kh = 0; kh < 3; kh++) {
            const float* pr = prb + kh * 40;
            float4 ev = *reinterpret_cast<const float4*>(pr);
            float e4 = pr[4];
            float4 od = *reinterpret_cast<const float4*>(pr + 20);
            conv_row_taps(acc, ev, e4, od, pw0 + (ic * 9 + kh * 3) * 32);
        }
    }

    const int oy = oy0 + y;
    const int ox0 = ox0t + 4 * xg;
    if (oy < 127 && ox0 < 128) {
        float* op = g_buf1 + ((size_t)b * 32 + g * 8) * (127 * 128) + (size_t)oy * 128 + (ox0 >> 1);
        conv_store<127 * 128, 64>(acc, op, bias, g_bns, g_bsh, g * 8);
    }
}

// ---------------------------------------------------------------------------
// conv2..5: 32 -> 32 ch.  128 thr (xg4 x y8 x g4), 16x8 tile, 4-ic x 8 phases,
// cp.async double-buffered fill (inputs AND weights are contiguous 16B copies
// thanks to the even/odd-split buffer layout).
// ---------------------------------------------------------------------------
template <int L, int IH, int IWS, int IE, int OH, int OWS, int OE, int TX>
__global__ void __launch_bounds__(128) conv32_kernel(const float* __restrict__ bias) {
    constexpr int SW_FL = 4 * 680;            // 2720 floats input region
    constexpr int BUF_FL = SW_FL + 1152;      // + weights = 3872 floats
    constexpr unsigned BUF_B = BUF_FL * 4u;
    constexpr unsigned IN_STEPB = 4u * IH * IWS * 4u; // bytes per 4-ic phase

    __shared__ __align__(16) float smem[2 * BUF_FL];

    const int b = blockIdx.y;
    const int tx = blockIdx.x % TX, ty = blockIdx.x / TX;
    const int ox0t = tx * 16, oy0 = ty * 8;
    const int ix0 = 2 * ox0t, iy0 = 2 * oy0;
    const float* in = (L == 0) ? g_buf1 : (L == 1) ? g_buf2 : (L == 2) ? g_buf3 : g_buf4;
    float* out = (L == 0) ? g_buf2 : (L == 1) ? g_buf3 : (L == 2) ? g_buf4 : g_buf5;
    const char* inb8 = (const char*)(in + (size_t)b * 32 * IH * IWS);
    const char* wt8 = (const char*)(g_wtl + L * 9216);

    // fill slots: 5 input (612 float4) + 3 weight (288 float4)
    unsigned in_src[5], in_dst[5], w_src[3], w_dst[3];
    bool vin[5], vw[3];
#pragma unroll
    for (int k = 0; k < 5; k++) {
        int s = threadIdx.x + k * 128;
        vin[k] = (s < 612);
        s = min(s, 611);
        int ic = s / 153, r = s - ic * 153;
        int row = r / 9, xq = r - row * 9;
        int gy = min(iy0 + row, IH - 1);
        int half = (xq < 5) ? ((ix0 >> 1) + 4 * xq) : (IE + (ix0 >> 1) + 4 * (xq - 5));
        in_src[k] = (unsigned)((ic * IH + gy) * IWS + half) * 4u;
        in_dst[k] = (unsigned)(ic * 680 + row * 40 + ((xq < 5) ? 4 * xq : 20 + 4 * (xq - 5))) * 4u;
    }
#pragma unroll
    for (int k = 0; k < 3; k++) {
        int idx = threadIdx.x + k * 128;
        vw[k] = (idx < 288);
        idx = min(idx, 287);
        w_src[k] = (unsigned)idx * 16u;
        w_dst[k] = (unsigned)(SW_FL * 4) + (unsigned)idx * 16u;
    }
    const uint32_t sb = smem_u32(smem);

    const int xg = threadIdx.x & 3;
    const int y = (threadIdx.x >> 2) & 7;
    const int g = threadIdx.x >> 5;
    unsigned long long acc[16];
#pragma unroll
    for (int i = 0; i < 16; i++) acc[i] = 0ULL;

    // prologue fill(0)
    {
        uint32_t base = sb;
#pragma unroll
        for (int k = 0; k < 5; k++) if (vin[k]) cp16(base + in_dst[k], inb8 + in_src[k]);
#pragma unroll
        for (int k = 0; k < 3; k++) if (vw[k]) cp16(base + w_dst[k], wt8 + w_src[k]);
        asm volatile("cp.async.commit_group;");
    }

    for (int ph = 0; ph < 8; ph++) {
        if (ph < 7) {
            uint32_t base = sb + (unsigned)((ph + 1) & 1) * BUF_B;
            unsigned io = (unsigned)(ph + 1) * IN_STEPB;
            unsigned wo = (unsigned)(ph + 1) * 4608u;
#pragma unroll
            for (int k = 0; k < 5; k++) if (vin[k]) cp16(base + in_dst[k], inb8 + in_src[k] + io);
#pragma unroll
            for (int k = 0; k < 3; k++) if (vw[k]) cp16(base + w_dst[k], wt8 + w_src[k] + wo);
            asm volatile("cp.async.commit_group;");
            asm volatile("cp.async.wait_group 1;");
        } else {
            asm volatile("cp.async.wait_group 0;");
        }
        __syncthreads();

        const float* sbf = smem + (ph & 1) * BUF_FL;
        const float* pw0 = sbf + SW_FL + g * 8;
#pragma unroll
        for (int ic = 0; ic < 4; ic++) {
            const float* prb = sbf + ic * 680 + (2 * y) * 40 + 4 * xg;
            const float* pw1 = pw0 + ic * 288;
#pragma unroll
            for (int kh = 0; kh < 3; kh++) {
                const float* pr = prb + kh * 40;
                float4 ev = *reinterpret_cast<const float4*>(pr);
                float e4 = pr[4];
                float4 od = *reinterpret_cast<const float4*>(pr + 20);
                conv_row_taps(acc, ev, e4, od, pw1 + kh * 96);
            }
        }
        __syncthreads(); // readers done before buf is refilled next phase
    }

    const int oy = oy0 + y;
    const int ox0 = ox0t + 4 * xg;
    // ox0 < OWS is load-bearing: without it, padding lanes of the 7-wide
    // layer write into the odd half / next row (the R8 corruption bug).
    if (oy < OH && ox0 < OWS) {
        const float* bns = g_bns + (L + 1) * 32;
        const float* bsh = g_bsh + (L + 1) * 32;
        float* op = out + ((size_t)b * 32 + g * 8) * (OH * OWS) + (size_t)oy * OWS + (ox0 >> 1);
        conv_store<OH * OWS, OE>(acc, op, bias, bns, bsh, g * 8);
    }
}

// ---------------------------------------------------------------------------
// FC(1568->20 relu) -> FC(20->10) -> Thomas tridiagonal solve (fp64) -> a,b,c.
// buf5 rows are even/odd-split: (row,x) -> row*8 + (x&1 ? 4+x/2 : x/2).
// ---------------------------------------------------------------------------
__global__ void __launch_bounds__(256) fc_kernel(const float* __restrict__ l1w,
                                                 const float* __restrict__ l1b,
                                                 const float* __restrict__ l2w,
                                                 const float* __restrict__ l2b) {
    __shared__ float s_y[1568];
    __shared__ float s_h1[20];
    __shared__ float s_ys[10];
    const int b = blockIdx.x;
    const float* yb = g_buf5 + (size_t)b * 32 * 7 * 8;
    for (int i = threadIdx.x; i < 1568; i += 256) {
        int oc = i / 49, r = i % 49;
        int row = r / 7, x = r - row * 7;
        int pos = row * 8 + ((x & 1) ? 4 + (x >> 1) : (x >> 1));
        s_y[i] = yb[oc * 56 + pos];
    }
    __syncthreads();

    const int warp = threadIdx.x >> 5, lane = threadIdx.x & 31;
    for (int j = warp; j < 20; j += 8) {
        float s = 0.f;
        const float* w = l1w + (size_t)j * 1568;
        for (int k = lane; k < 1568; k += 32) s += s_y[k] * w[k];
#pragma unroll
        for (int o = 16; o > 0; o >>= 1) s += __shfl_down_sync(0xffffffffu, s, o);
        if (lane == 0) s_h1[j] = fmaxf(s + l1b[j], 0.f);
    }
    __syncthreads();

    if (threadIdx.x < 10) {
        float s = l2b[threadIdx.x];
        const float* w = l2w + threadIdx.x * 20;
#pragma unroll
        for (int j = 0; j < 20; j++) s += s_h1[j] * w[j];
        s_ys[threadIdx.x] = s;
    }
    __syncthreads();

    if (threadIdx.x == 0) {
        const double h = 1.0 / 9.0;
        double ys[10];
#pragma unroll
        for (int i = 0; i < 10; i++) ys[i] = (double)s_ys[i];
        double d[8], cp[8];
        for (int i = 0; i < 8; i++)
            d[i] = (6.0 / (h * h)) * (ys[i + 2] - 2.0 * ys[i + 1] + ys[i]);
        cp[0] = 0.25;
        d[0] *= 0.25;
        for (int i = 1; i < 8; i++) {
            double m = 4.0 - cp[i - 1];
            cp[i] = 1.0 / m;
            d[i] = (d[i] - d[i - 1]) / m;
        }
        double M[10];
        M[0] = 0.0;
        M[9] = 0.0;
        M[8] = d[7];
        for (int i = 6; i >= 0; i--) M[i + 1] = d[i] - cp[i] * M[i + 2];
        float* cf = g_coef + b * 27;
        for (int i = 0; i < 9; i++) {
            cf[i] = (float)((M[i + 1] - M[i]) / (6.0 * h));
            cf[9 + i] = (float)(M[i] * 0.5);
            cf[18 + i] = (float)((ys[i + 1] - ys[i]) / h - (M[i + 1] + 2.0 * M[i]) * (h / 6.0));
        }
    }
}

// ---------------------------------------------------------------------------
// eval: fast bucket via x*9; exact __fdiv_rn fallback only near knots.
// ---------------------------------------------------------------------------
__device__ __forceinline__ float evalpix(float x, const float* __restrict__ sc) {
    const float h = 1.0f / 9.0f;
    float tf = fminf(fmaxf(x * 9.0f, 0.f), 8.f);
    int xi = (int)tf;
    float fr = tf - (float)xi;
    if (fr < 1e-4f || fr > 0.9999f) {
        float te = fminf(fmaxf(__fdiv_rn(x, h), 0.f), 8.f);
        xi = (int)te;
    }
    float xf = x - (float)xi * h;
    return ((sc[xi] * xf + sc[9 + xi]) * xf + sc[18 + xi]) * xf;
}

__global__ void __launch_bounds__(256) eval_kernel(const float* __restrict__ in,
                                                   float* __restrict__ out) {
    __shared__ float s_c[27];
    const int b = blockIdx.y;
    if (threadIdx.x < 27) s_c[threadIdx.x] = g_coef[b * 27 + threadIdx.x];
    __syncthreads();
    const int N = 3 * 255 * 255;
    const float* ib = in + (size_t)b * N;
    float* ob = out + (size_t)b * N;
    const int mis = (4 - ((3 * b) & 3)) & 3;
    const int nv = (N - mis) >> 2;
    const float4* iv = reinterpret_cast<const float4*>(ib + mis);
    float4* ov = reinterpret_cast<float4*>(ob + mis);
    for (int v = blockIdx.x * 256 + threadIdx.x; v < nv; v += gridDim.x * 256) {
        float4 x = iv[v];
        float4 r;
        r.x = evalpix(x.x, s_c);
        r.y = evalpix(x.y, s_c);
        r.z = evalpix(x.z, s_c);
        r.w = evalpix(x.w, s_c);
        ov[v] = r;
    }
    const int tail = N - mis - 4 * nv;
    if (blockIdx.x == 0 && threadIdx.x < mis + tail) {
        int t = threadIdx.x;
        int i = (t < mis) ? t : (mis + 4 * nv + (t - mis));
        ob[i] = evalpix(ib[i], s_c);
    }
}

// ---------------------------------------------------------------------------
extern "C" void kernel_launch(void* const* d_in, const int* in_sizes, int n_in,
                              void* d_out, int out_size) {
    const float* batch = (const float*)d_in[0];
    const float* c1w = (const float*)d_in[1];
    const float* c1b = (const float*)d_in[2];
    const float* cw = (const float*)d_in[3];
    const float* cb = (const float*)d_in[4];
    const float* bng = (const float*)d_in[5];
    const float* bnb = (const float*)d_in[6];
    const float* bnm = (const float*)d_in[7];
    const float* bnv = (const float*)d_in[8];
    const float* l1w = (const float*)d_in[9];
    const float* l1b = (const float*)d_in[10];
    const float* l2w = (const float*)d_in[11];
    const float* l2b = (const float*)d_in[12];
    float* out = (float*)d_out;

    prep_kernel<<<64, 256>>>(c1w, cw, bng, bnb, bnm, bnv);
    conv1_kernel<<<dim3(64, 64), 256>>>(batch, c1b);
    //            L  IH  IWS IE  OH  OWS OE  TX
    conv32_kernel<0, 127, 128, 64, 63, 64, 32, 4><<<dim3(32, 64), 128>>>(cb + 0);
    conv32_kernel<1, 63, 64, 32, 31, 32, 16, 2><<<dim3(8, 64), 128>>>(cb + 32);
    conv32_kernel<2, 31, 32, 16, 15, 16, 8, 1><<<dim3(2, 64), 128>>>(cb + 64);
    conv32_kernel<3, 15, 16, 8, 7, 8, 4, 1><<<dim3(1, 64), 128>>>(cb + 96);
    fc_kernel<<<64, 256>>>(l1w, l1b, l2w, l2b);
    eval_kernel<<<dim3(191, 64), 256>>>(batch, out);
}